// round 16
// baseline (speedup 1.0000x reference)
#include <cuda_runtime.h>
#include <cstdint>
#include <cstddef>
#include <math.h>

// Problem constants
#define T_SEQ 1024
#define BATCH 64
#define HID   512
#define G4    2048
#define H_T_STRIDE   (BATCH*HID)
#define G_T_STRIDE   (BATCH*G4)
#define OUT_T_STRIDE (BATCH*2*HID)
#define HIDH_OFF ((size_t)T_SEQ*OUT_T_STRIDE)
#define HIDC_OFF (HIDH_OFF + (size_t)2*BATCH*2*HID)

// ---------------- scratch (device globals; no allocations allowed) -----------
__device__ float g_gatesF[(size_t)T_SEQ*BATCH*G4];
__device__ float g_gatesB[(size_t)T_SEQ*BATCH*G4];
__device__ float g_H0buf[(size_t)T_SEQ*BATCH*HID];
__device__ float g_H1buf[(size_t)T_SEQ*BATCH*HID];
// per-CTA completion flags: [dir][cta] padded to 128B lines
__device__ unsigned g_flag[2 * 64 * 32];

// ---------------- helpers ----------------------------------------------------
__device__ __forceinline__ uint32_t f2tf32(float f) {
    uint32_t r;
    asm("cvt.rna.tf32.f32 %0, %1;" : "=r"(r) : "f"(f));
    return r;
}
__device__ __forceinline__ void cp16(void* smem_dst, const void* gsrc) {
    uint32_t s = (uint32_t)__cvta_generic_to_shared(smem_dst);
    asm volatile("cp.async.cg.shared.global [%0], [%1], 16;" :: "r"(s), "l"(gsrc));
}
#define CP_COMMIT() asm volatile("cp.async.commit_group;" ::: "memory")
#define CP_WAITN(n) asm volatile("cp.async.wait_group %0;" :: "n"(n) : "memory")

__device__ __forceinline__ void mma8(float* c, const uint32_t* a, uint32_t b0, uint32_t b1) {
    asm volatile(
        "mma.sync.aligned.m16n8k8.row.col.f32.tf32.tf32.f32 "
        "{%0,%1,%2,%3}, {%4,%5,%6,%7}, {%8,%9}, {%0,%1,%2,%3};"
        : "+f"(c[0]), "+f"(c[1]), "+f"(c[2]), "+f"(c[3])
        : "r"(a[0]), "r"(a[1]), "r"(a[2]), "r"(a[3]), "r"(b0), "r"(b1));
}

// HW tanh: single MUFU op on sm_75+.
__device__ __forceinline__ float tanh_fast(float x) {
    float y;
    asm("tanh.approx.f32 %0, %1;" : "=f"(y) : "f"(x));
    return y;
}
__device__ __forceinline__ float sigm(float x) {
    return 0.5f + 0.5f * tanh_fast(0.5f * x);
}

__device__ __forceinline__ void flag_release(unsigned* p, unsigned v) {
    asm volatile("st.release.gpu.global.u32 [%0], %1;" :: "l"(p), "r"(v) : "memory");
}
__device__ __forceinline__ unsigned flag_acquire(const unsigned* p) {
    unsigned v;
    asm volatile("ld.acquire.gpu.global.u32 %0, [%1];" : "=r"(v) : "l"(p));
    return v;
}

#define SROW 36      // pre_gemm 32-K tile row pad
#define WROW 516     // persistent W row pad (conflict-free)
#define STG  4608    // pre_gemm stage size in floats (128*36)

// ================= precompute GEMM: C[M,2048] = X[M,512] @ W[2048,512]^T =====
// CTA tile 128x128, 256 threads (8 warps, warp tile 32x64). z selects X/W/C.
// 3-stage cp.async pipeline, race-free ordering: wait -> barrier -> issue/compute.
__global__ __launch_bounds__(256) void pre_gemm(const float* __restrict__ X0,
                                                const float* __restrict__ X1,
                                                const float* __restrict__ W0,
                                                const float* __restrict__ W1,
                                                float* __restrict__ C0,
                                                float* __restrict__ C1) {
    extern __shared__ float smem[];
    float* sA = smem;              // 3 * 4608
    float* sB = smem + 3 * STG;    // 3 * 4608
    const float* X = blockIdx.z ? X1 : X0;
    const float* W = blockIdx.z ? W1 : W0;
    float* C = blockIdx.z ? C1 : C0;

    int n0 = blockIdx.x * 128;
    size_t m0 = (size_t)blockIdx.y * 128;

    int tid = threadIdx.x, warp = tid >> 5, lane = tid & 31;
    int g = lane >> 2, t4 = lane & 3;
    int wm = (warp & 3) * 32, wn = (warp >> 2) * 64;
    int lr = tid >> 1, lc = (tid & 1) * 16;

    const float* Ag = X + (m0 + lr) * 512 + lc;
    const float* Bg = W + (size_t)(n0 + lr) * 512 + lc;

    float acc[2][8][4];
#pragma unroll
    for (int i = 0; i < 2; i++)
#pragma unroll
        for (int j = 0; j < 8; j++)
#pragma unroll
            for (int k = 0; k < 4; k++) acc[i][j][k] = 0.f;

    // prologue: chunks 0 and 1
#pragma unroll
    for (int st = 0; st < 2; st++) {
#pragma unroll
        for (int q = 0; q < 4; q++) {
            cp16(&sA[st * STG + lr * SROW + lc + q * 4], Ag + st * 32 + q * 4);
            cp16(&sB[st * STG + lr * SROW + lc + q * 4], Bg + st * 32 + q * 4);
        }
        CP_COMMIT();
    }

    for (int kc = 0; kc < 16; kc++) {
        if (kc < 15) CP_WAITN(1);
        else         CP_WAITN(0);
        __syncthreads();
        if (kc + 2 < 16) {
            int ko = (kc + 2) * 32;
            int st = ((kc + 2) % 3) * STG;
#pragma unroll
            for (int q = 0; q < 4; q++) {
                cp16(&sA[st + lr * SROW + lc + q * 4], Ag + ko + q * 4);
                cp16(&sB[st + lr * SROW + lc + q * 4], Bg + ko + q * 4);
            }
            CP_COMMIT();
        }
        const float* a_s = sA + (kc % 3) * STG;
        const float* b_s = sB + (kc % 3) * STG;
#pragma unroll
        for (int kk = 0; kk < 4; kk++) {
            int k0 = kk * 8;
            uint32_t a[2][4];
#pragma unroll
            for (int mt = 0; mt < 2; mt++) {
                const float* p = a_s + (wm + mt * 16 + g) * SROW + k0 + t4;
                a[mt][0] = f2tf32(p[0]);
                a[mt][1] = f2tf32(p[8 * SROW]);
                a[mt][2] = f2tf32(p[4]);
                a[mt][3] = f2tf32(p[8 * SROW + 4]);
            }
#pragma unroll
            for (int nt = 0; nt < 8; nt++) {
                const float* p = b_s + (wn + nt * 8 + g) * SROW + k0 + t4;
                uint32_t b0 = f2tf32(p[0]);
                uint32_t b1 = f2tf32(p[4]);
#pragma unroll
                for (int mt = 0; mt < 2; mt++) mma8(acc[mt][nt], a[mt], b0, b1);
            }
        }
    }

#pragma unroll
    for (int mt = 0; mt < 2; mt++) {
        size_t row = m0 + wm + mt * 16 + g;
#pragma unroll
        for (int nt = 0; nt < 8; nt++) {
            int col = n0 + wn + nt * 8 + t4 * 2;
            *(float2*)(C + row * 2048 + col) = make_float2(acc[mt][nt][0], acc[mt][nt][1]);
            *(float2*)(C + (row + 8) * 2048 + col) = make_float2(acc[mt][nt][2], acc[mt][nt][3]);
        }
    }
}

// ================= persistent recurrence (both dirs per CTA) =================
struct PersistArgs {
    const float* W[2];
    const float* Gx[2];
    float* Hout[2];
    float* hid_h[2];
    float* hid_c[2];
    int ldh;
};

__global__ void reset_bar() {
    int i = threadIdx.x + blockIdx.x * blockDim.x;
    if (i < 2 * 64 * 32) g_flag[i] = 0;
}

// no-op: pads the launch index so ncu lands on lstm_persist at OUR index 3.
__global__ void noop() {}

// grid (64): each CTA owns 8 hidden cols of BOTH directions and alternates
// d0-phase / d1-phase each round. The flag-wait for dir d executes after the
// other direction's full compute phase -> handoff latency hidden.
// 512 threads = 16 warps = 4 batch-quarters (mg) x 4 K-quarters (kq).
// Warp tile m16 batch x n32 gates x k128; h read directly from L2 (__ldcg);
// both dirs' W slices resident in smem (tf32).
__global__ __launch_bounds__(512) void lstm_persist(PersistArgs args) {
    extern __shared__ float smem[];
    uint32_t* sWu = (uint32_t*)smem;              // 2 * 32 * WROW
    float* sRed = smem + 2 * 32 * WROW;           // 4 * 64*34
    float* sGx = sRed + 4 * 64 * 34;              // 2 * 64*36

    int j0 = blockIdx.x * 8;
    int tid = threadIdx.x, warp = tid >> 5, lane = tid & 31;
    int g = lane >> 2, t4 = lane & 3;
    int mg = warp & 3, kq = warp >> 2;

    int ldh = args.ldh;
    size_t tstr = (size_t)64 * ldh;

    // preload W slices for BOTH dirs (tf32 bits). gate-row n = gs*8 + jj.
    for (int i = tid; i < 2 * 32 * 512; i += 512) {
        int d = i >> 14;
        int r = i & 16383;
        int n = r >> 9, k = r & 511;
        int gs = n >> 3, jj = n & 7;
        sWu[(d * 32 + n) * WROW + k] =
            f2tf32(args.W[d][(size_t)(gs * 512 + j0 + jj) * 512 + k]);
    }
    __syncthreads();

    float creg[2] = {0.f, 0.f};
    int eb = tid >> 3, ej = tid & 7;          // elementwise cell (batch, col)
    int pgs = (tid & 7) >> 1, pjj = (tid & 1) * 4;  // gx prefetch mapping

    for (int s = 0; s < T_SEQ; s++) {
        int tt0 = s, tt1 = T_SEQ - 1 - s;

        // prefetch both dirs' Gx slices (2 separate commit groups)
        {
            const float* s0 = args.Gx[0] + (size_t)tt0 * G_T_STRIDE + (size_t)eb * 2048
                              + pgs * 512 + j0 + pjj;
            cp16(sGx + eb * 36 + pgs * 8 + pjj, s0);
            CP_COMMIT();
            const float* s1 = args.Gx[1] + (size_t)tt1 * G_T_STRIDE + (size_t)eb * 2048
                              + pgs * 512 + j0 + pjj;
            cp16(sGx + 2304 + eb * 36 + pgs * 8 + pjj, s1);
            CP_COMMIT();
        }

#pragma unroll
        for (int d = 0; d < 2; d++) {
            int t = d == 0 ? tt0 : tt1;
            float* Hb = args.Hout[d];
            unsigned* flags = &g_flag[d * 64 * 32];

            float acc[4][4];
#pragma unroll
            for (int j = 0; j < 4; j++)
#pragma unroll
                for (int k = 0; k < 4; k++) acc[j][k] = 0.f;

            if (s > 0) {
                // wait: all 64 CTAs finished this dir's step s-1
                if (tid < 64) {
                    const unsigned* f = &flags[tid * 32];
                    while (flag_acquire(f) < (unsigned)s) __nanosleep(20);
                }
                __syncthreads();

                int tp = (d == 0) ? t - 1 : t + 1;
                const float* A = Hb + (size_t)tp * tstr;
                const float* pa0 = A + (size_t)(mg * 16 + g) * ldh + kq * 128 + t4;
                const float* pa1 = pa0 + (size_t)8 * ldh;
#pragma unroll
                for (int k8 = 0; k8 < 16; k8++) {
                    int ko = k8 * 8;
                    uint32_t a[4];
                    a[0] = f2tf32(__ldcg(pa0 + ko));
                    a[1] = f2tf32(__ldcg(pa1 + ko));
                    a[2] = f2tf32(__ldcg(pa0 + ko + 4));
                    a[3] = f2tf32(__ldcg(pa1 + ko + 4));
                    int k0 = kq * 128 + ko;
#pragma unroll
                    for (int nt = 0; nt < 4; nt++) {
                        const uint32_t* p = sWu + (d * 32 + nt * 8 + g) * WROW + k0 + t4;
                        mma8(acc[nt], a, p[0], p[4]);
                    }
                }
            }

            // stage K-split partials: sRed[kq][batch][gate]
            {
                float* r0 = sRed + kq * (64 * 34) + (mg * 16 + g) * 34;
                float* r1 = r0 + 8 * 34;
#pragma unroll
                for (int nt = 0; nt < 4; nt++) {
                    int col = nt * 8 + t4 * 2;
                    *(float2*)(r0 + col) = make_float2(acc[nt][0], acc[nt][1]);
                    *(float2*)(r1 + col) = make_float2(acc[nt][2], acc[nt][3]);
                }
            }
            if (d == 0) CP_WAITN(1);   // this dir's gx landed (other still pending)
            else        CP_WAITN(0);
            __syncthreads();

            // elementwise LSTM: one cell per thread
            float* hrow = Hb + (size_t)t * tstr;
            bool wh = (d == 0) ? (s == T_SEQ - 1) : (s == 0);
            {
                const float* rb = sRed + eb * 34;
                const float* gx = sGx + d * 2304 + eb * 36;
                float gsum[4];
#pragma unroll
                for (int gs2 = 0; gs2 < 4; gs2++) {
                    int go = gs2 * 8 + ej;
                    gsum[gs2] = rb[go] + rb[64 * 34 + go] + rb[2 * 64 * 34 + go]
                              + rb[3 * 64 * 34 + go] + gx[go];
                }
                float cn = sigm(gsum[1]) * creg[d] + sigm(gsum[0]) * tanh_fast(gsum[2]);
                float hn = sigm(gsum[3]) * tanh_fast(cn);
                creg[d] = cn;
                int col = j0 + ej;
                hrow[(size_t)eb * ldh + col] = hn;
                if (wh) {
                    args.hid_h[d][eb * 1024 + col] = hn;
                    args.hid_c[d][eb * 1024 + col] = cn;
                }
            }

            // publish: all stores -> syncthreads -> cumulative release store
            __syncthreads();
            if (tid == 0)
                flag_release(&g_flag[d * 64 * 32 + blockIdx.x * 32], (unsigned)(s + 1));
        }
    }
}

// ---------------- host -------------------------------------------------------
extern "C" void kernel_launch(void* const* d_in, const int* in_sizes, int n_in,
                              void* d_out, int out_size) {
    const float* x     = (const float*)d_in[0];
    const float* wihf0 = (const float*)d_in[1];
    const float* whhf0 = (const float*)d_in[2];
    const float* wihf1 = (const float*)d_in[3];
    const float* whhf1 = (const float*)d_in[4];
    const float* wihb0 = (const float*)d_in[5];
    const float* whhb0 = (const float*)d_in[6];
    const float* wihb1 = (const float*)d_in[7];
    const float* whhb1 = (const float*)d_in[8];
    float* out = (float*)d_out;

    float *gates0, *gates1, *H0, *H1;
    cudaGetSymbolAddress((void**)&gates0, g_gatesF);
    cudaGetSymbolAddress((void**)&gates1, g_gatesB);
    cudaGetSymbolAddress((void**)&H0, g_H0buf);
    cudaGetSymbolAddress((void**)&H1, g_H1buf);

    const int PRE_SMEM = 6 * STG * 4;  // 110592
    const int PERSIST_SMEM = (2 * 32 * WROW + 4 * 64 * 34 + 2 * 64 * 36) * 4;  // 185344
    cudaFuncSetAttribute(pre_gemm, cudaFuncAttributeMaxDynamicSharedMemorySize, PRE_SMEM);
    cudaFuncSetAttribute(lstm_persist, cudaFuncAttributeMaxDynamicSharedMemorySize, PERSIST_SMEM);

    // Launch map (harness prepends 2 internal launches; ncu -s 5 captures OUR #3):
    //  #0 preL0(z2)  #1 reset  #2 noop  #3 persistL0  #4 preL1a  #5 preL1b
    //  #6 reset  #7 persistL1
    pre_gemm<<<dim3(16, 512, 2), 256, PRE_SMEM>>>(x, x, wihf0, wihb0, gates0, gates1);
    reset_bar<<<16, 256>>>();
    noop<<<1, 1>>>();
    {
        PersistArgs pa;
        pa.W[0] = whhf0;  pa.W[1] = whhb0;
        pa.Gx[0] = gates0; pa.Gx[1] = gates1;
        pa.Hout[0] = H0;  pa.Hout[1] = H1;
        pa.hid_h[0] = out + HIDH_OFF;       pa.hid_h[1] = out + HIDH_OFF + 512;
        pa.hid_c[0] = out + HIDC_OFF;       pa.hid_c[1] = out + HIDC_OFF + 512;
        pa.ldh = 512;
        lstm_persist<<<64, 512, PERSIST_SMEM>>>(pa);
    }

    // layer 1: different inputs per direction -> two z=1 launches
    pre_gemm<<<dim3(16, 512, 1), 256, PRE_SMEM>>>(H0, H0, wihf1, wihf1, gates0, gates0);
    pre_gemm<<<dim3(16, 512, 1), 256, PRE_SMEM>>>(H1, H1, wihb1, wihb1, gates1, gates1);
    reset_bar<<<16, 256>>>();
    {
        PersistArgs pa;
        pa.W[0] = whhf1;  pa.W[1] = whhb1;
        pa.Gx[0] = gates0; pa.Gx[1] = gates1;
        pa.Hout[0] = out; pa.Hout[1] = out + 512;
        pa.hid_h[0] = out + HIDH_OFF + 65536;  pa.hid_h[1] = out + HIDH_OFF + 65536 + 512;
        pa.hid_c[0] = out + HIDC_OFF + 65536;  pa.hid_c[1] = out + HIDC_OFF + 65536 + 512;
        pa.ldh = 1024;
        lstm_persist<<<64, 512, PERSIST_SMEM>>>(pa);
    }
    (void)in_sizes; (void)n_in; (void)out_size;
}

// round 17
// speedup vs baseline: 1.6772x; 1.6772x over previous
#include <cuda_runtime.h>
#include <cstdint>
#include <cstddef>
#include <math.h>

// Problem constants
#define T_SEQ 1024
#define BATCH 64
#define HID   512
#define G4    2048
#define H_T_STRIDE   (BATCH*HID)
#define G_T_STRIDE   (BATCH*G4)
#define OUT_T_STRIDE (BATCH*2*HID)
#define HIDH_OFF ((size_t)T_SEQ*OUT_T_STRIDE)
#define HIDC_OFF (HIDH_OFF + (size_t)2*BATCH*2*HID)

// ---------------- scratch (device globals; no allocations allowed) -----------
__device__ float g_gatesF[(size_t)T_SEQ*BATCH*G4];
__device__ float g_gatesB[(size_t)T_SEQ*BATCH*G4];
__device__ float g_H0buf[(size_t)T_SEQ*BATCH*HID];
__device__ float g_H1buf[(size_t)T_SEQ*BATCH*HID];
// per-CTA completion flags: [dir][cta] padded to 128B lines
__device__ unsigned g_flag[2 * 64 * 32];

// ---------------- helpers ----------------------------------------------------
__device__ __forceinline__ uint32_t f2tf32(float f) {
    uint32_t r;
    asm("cvt.rna.tf32.f32 %0, %1;" : "=r"(r) : "f"(f));
    return r;
}
__device__ __forceinline__ void cp16(void* smem_dst, const void* gsrc) {
    uint32_t s = (uint32_t)__cvta_generic_to_shared(smem_dst);
    asm volatile("cp.async.cg.shared.global [%0], [%1], 16;" :: "r"(s), "l"(gsrc));
}
#define CP_COMMIT() asm volatile("cp.async.commit_group;" ::: "memory")
#define CP_WAITN(n) asm volatile("cp.async.wait_group %0;" :: "n"(n) : "memory")

__device__ __forceinline__ void mma8(float* c, const uint32_t* a, uint32_t b0, uint32_t b1) {
    asm volatile(
        "mma.sync.aligned.m16n8k8.row.col.f32.tf32.tf32.f32 "
        "{%0,%1,%2,%3}, {%4,%5,%6,%7}, {%8,%9}, {%0,%1,%2,%3};"
        : "+f"(c[0]), "+f"(c[1]), "+f"(c[2]), "+f"(c[3])
        : "r"(a[0]), "r"(a[1]), "r"(a[2]), "r"(a[3]), "r"(b0), "r"(b1));
}

// HW tanh: single MUFU op on sm_75+.
__device__ __forceinline__ float tanh_fast(float x) {
    float y;
    asm("tanh.approx.f32 %0, %1;" : "=f"(y) : "f"(x));
    return y;
}
__device__ __forceinline__ float sigm(float x) {
    return 0.5f + 0.5f * tanh_fast(0.5f * x);
}

__device__ __forceinline__ void flag_release(unsigned* p, unsigned v) {
    asm volatile("st.release.gpu.global.u32 [%0], %1;" :: "l"(p), "r"(v) : "memory");
}
__device__ __forceinline__ unsigned flag_acquire(const unsigned* p) {
    unsigned v;
    asm volatile("ld.acquire.gpu.global.u32 %0, [%1];" : "=r"(v) : "l"(p));
    return v;
}

#define SROW 36      // pre_gemm 32-K tile row pad
#define AROW 516     // persistent A (h) row pad — conflict-free for 32-bit LDS
#define WROW 520     // persistent W row pad (==8 mod 32) — conflict-free LDS.64

// ================= precompute GEMM: C[M,2048] = X[M,512] @ W[2048,512]^T =====
// CTA tile 128x128, 256 threads (8 warps, warp tile 32x64). z selects X/W/C.
// Proven 2-stage cp.async pipeline (R7 baseline).
__global__ __launch_bounds__(256) void pre_gemm(const float* __restrict__ X0,
                                                const float* __restrict__ X1,
                                                const float* __restrict__ W0,
                                                const float* __restrict__ W1,
                                                float* __restrict__ C0,
                                                float* __restrict__ C1) {
    extern __shared__ float smem[];
    float* sA = smem;            // 2 * 128*36
    float* sB = smem + 9216;
    const float* X = blockIdx.z ? X1 : X0;
    const float* W = blockIdx.z ? W1 : W0;
    float* C = blockIdx.z ? C1 : C0;

    int n0 = blockIdx.x * 128;
    size_t m0 = (size_t)blockIdx.y * 128;

    int tid = threadIdx.x, warp = tid >> 5, lane = tid & 31;
    int g = lane >> 2, t4 = lane & 3;
    int wm = (warp & 3) * 32, wn = (warp >> 2) * 64;
    int lr = tid >> 1, lc = (tid & 1) * 16;

    const float* Ag = X + (m0 + lr) * 512 + lc;
    const float* Bg = W + (size_t)(n0 + lr) * 512 + lc;

    float acc[2][8][4];
#pragma unroll
    for (int i = 0; i < 2; i++)
#pragma unroll
        for (int j = 0; j < 8; j++)
#pragma unroll
            for (int k = 0; k < 4; k++) acc[i][j][k] = 0.f;

#pragma unroll
    for (int q = 0; q < 4; q++) {
        cp16(&sA[lr * SROW + lc + q * 4], Ag + q * 4);
        cp16(&sB[lr * SROW + lc + q * 4], Bg + q * 4);
    }
    CP_COMMIT();

    for (int kc = 0; kc < 16; kc++) {
        if (kc < 15) {
            int ko = (kc + 1) * 32;
            int st1 = ((kc + 1) & 1) * 4608;
#pragma unroll
            for (int q = 0; q < 4; q++) {
                cp16(&sA[st1 + lr * SROW + lc + q * 4], Ag + ko + q * 4);
                cp16(&sB[st1 + lr * SROW + lc + q * 4], Bg + ko + q * 4);
            }
            CP_COMMIT();
            CP_WAITN(1);
        } else {
            CP_WAITN(0);
        }
        __syncthreads();
        const float* a_s = sA + (kc & 1) * 4608;
        const float* b_s = sB + (kc & 1) * 4608;
#pragma unroll
        for (int kk = 0; kk < 4; kk++) {
            int k0 = kk * 8;
            uint32_t a[2][4];
#pragma unroll
            for (int mt = 0; mt < 2; mt++) {
                const float* p = a_s + (wm + mt * 16 + g) * SROW + k0 + t4;
                a[mt][0] = f2tf32(p[0]);
                a[mt][1] = f2tf32(p[8 * SROW]);
                a[mt][2] = f2tf32(p[4]);
                a[mt][3] = f2tf32(p[8 * SROW + 4]);
            }
#pragma unroll
            for (int nt = 0; nt < 8; nt++) {
                const float* p = b_s + (wn + nt * 8 + g) * SROW + k0 + t4;
                uint32_t b0 = f2tf32(p[0]);
                uint32_t b1 = f2tf32(p[4]);
#pragma unroll
                for (int mt = 0; mt < 2; mt++) mma8(acc[mt][nt], a[mt], b0, b1);
            }
        }
        __syncthreads();
    }

#pragma unroll
    for (int mt = 0; mt < 2; mt++) {
        size_t row = m0 + wm + mt * 16 + g;
#pragma unroll
        for (int nt = 0; nt < 8; nt++) {
            int col = n0 + wn + nt * 8 + t4 * 2;
            *(float2*)(C + row * 2048 + col) = make_float2(acc[mt][nt][0], acc[mt][nt][1]);
            *(float2*)(C + (row + 8) * 2048 + col) = make_float2(acc[mt][nt][2], acc[mt][nt][3]);
        }
    }
}

// ================= persistent recurrence =====================================
struct PersistArgs {
    const float* W[2];
    const float* Gx[2];
    float* Hout[2];
    float* hid_h[2];
    float* hid_c[2];
    int ldh;
};

__global__ void reset_bar() {
    int i = threadIdx.x + blockIdx.x * blockDim.x;
    if (i < 2 * 64 * 32) g_flag[i] = 0;
}

// no-op: pads the launch index so ncu lands on lstm_persist at OUR index 3.
__global__ void noop() {}

// grid (64, 2): 64 CTAs per direction, each owns 8 hidden cols (32 gate rows).
// 256 threads = 8 warps = 4 m-groups x 2 K-halves; each warp owns a private A
// region (16 rows x 256 k) -> no block syncs inside the GEMM.
// W stored PAIRED in smem: within each k-octet, (t4, t4+4) adjacent -> one
// LDS.64 per mma8 instead of two scalar LDS. WROW==8 (mod 32): conflict-free.
// Step sync: R7 protocol — distributed flags, tid<64 poll + nanosleep.
__global__ __launch_bounds__(256) void lstm_persist(PersistArgs args) {
    extern __shared__ float smem[];
    float* sA = smem;                               // 64 * AROW floats
    uint32_t* sWu = (uint32_t*)(smem + 64 * AROW);  // 32 * WROW
    float* sRed = smem + 64 * AROW + 32 * WROW;     // 2 * 64*34
    float* sGx = sRed + 2 * 64 * 34;                // 64 * 36

    int dir = blockIdx.y;
    int j0 = blockIdx.x * 8;
    int tid = threadIdx.x, warp = tid >> 5, lane = tid & 31;
    int g = lane >> 2, t4 = lane & 3;
    int mg = warp & 3, kh = warp >> 2;

    const float* W = args.W[dir];
    const float* GxB = args.Gx[dir];
    float* Hb = args.Hout[dir];
    float* hidh = args.hid_h[dir];
    float* hidc = args.hid_c[dir];
    int ldh = args.ldh;
    size_t tstr = (size_t)64 * ldh;

    unsigned* flags = &g_flag[dir * 64 * 32];
    unsigned* myflag = &flags[blockIdx.x * 32];

    // preload W slice (tf32 bits), PAIRED k layout:
    // k' = (k & ~7) | ((k & 3) << 1) | ((k >> 2) & 1)
    for (int i = tid; i < 32 * 512; i += 256) {
        int n = i >> 9, k = i & 511;
        int gs = n >> 3, jj = n & 7;
        int kp = (k & ~7) | ((k & 3) << 1) | ((k >> 2) & 1);
        sWu[n * WROW + kp] = f2tf32(W[(size_t)(gs * 512 + j0 + jj) * 512 + k]);
    }
    __syncthreads();

    float creg[2] = {0.f, 0.f};

    // per-warp private A addressing: rows mg*16..+16, k kh*256..+256
    int arow = mg * 16 + (lane >> 1);
    int acol = kh * 256 + (lane & 1) * 32;
    float* a_s_base = sA + arow * AROW + acol;

    // gx prefetch mapping: thread handles segment (b, gate): 8 floats
    int pb = tid >> 2, pg = tid & 3;

    for (int s = 0; s < T_SEQ; s++) {
        int t = (dir == 0) ? s : (T_SEQ - 1 - s);

        // prefetch this step's Gx slice into smem (independent of barrier)
        {
            const float* src = GxB + (size_t)t * G_T_STRIDE + (size_t)pb * 2048 + pg * 512 + j0;
            float* dst = sGx + pb * 36 + pg * 8;
            cp16(dst, src);
            cp16(dst + 4, src + 4);
            CP_COMMIT();
        }

        float acc[4][4];
#pragma unroll
        for (int j = 0; j < 4; j++)
#pragma unroll
            for (int k = 0; k < 4; k++) acc[j][k] = 0.f;

        if (s > 0) {
            // wait for all CTAs (this dir) to have finished step s-1
            if (tid < 64) {
                const unsigned* f = &flags[tid * 32];
                while (flag_acquire(f) < (unsigned)s) __nanosleep(20);
            }
            __syncthreads();

            int tp = (dir == 0) ? t - 1 : t + 1;
            const float* a_g_base = Hb + (size_t)tp * tstr + (size_t)arow * ldh + acol;
#pragma unroll
            for (int sub = 0; sub < 4; sub++) {
#pragma unroll
                for (int q = 0; q < 8; q++)
                    cp16(a_s_base + sub * 64 + q * 4, a_g_base + sub * 64 + q * 4);
                CP_COMMIT();
            }
#pragma unroll
            for (int sub = 0; sub < 4; sub++) {
                if (sub == 0) CP_WAITN(3);
                else if (sub == 1) CP_WAITN(2);
                else if (sub == 2) CP_WAITN(1);
                else CP_WAITN(0);
                __syncwarp();
                int kb = kh * 256 + sub * 64;
#pragma unroll
                for (int k8 = 0; k8 < 8; k8++) {
                    int k0 = kb + k8 * 8;
                    const float* pa = sA + (mg * 16 + g) * AROW + k0 + t4;
                    uint32_t a[4];
                    a[0] = f2tf32(pa[0]);
                    a[1] = f2tf32(pa[8 * AROW]);
                    a[2] = f2tf32(pa[4]);
                    a[3] = f2tf32(pa[8 * AROW + 4]);
#pragma unroll
                    for (int nt = 0; nt < 4; nt++) {
                        const uint2* p = (const uint2*)(sWu + (nt * 8 + g) * WROW + k0 + t4 * 2);
                        uint2 b = *p;
                        mma8(acc[nt], a, b.x, b.y);
                    }
                }
            }
        }

        // stage K-split partials: sRed[kh][row][n]
        {
            float* r0 = sRed + kh * (64 * 34) + (mg * 16 + g) * 34;
            float* r1 = r0 + 8 * 34;
#pragma unroll
            for (int nt = 0; nt < 4; nt++) {
                int col = nt * 8 + t4 * 2;
                *(float2*)(r0 + col) = make_float2(acc[nt][0], acc[nt][1]);
                *(float2*)(r1 + col) = make_float2(acc[nt][2], acc[nt][3]);
            }
        }
        CP_WAITN(0);          // ensure gx prefetch landed (no-op if drained)
        __syncthreads();

        // elementwise LSTM for cols [j0, j0+8)
        float* hrow = Hb + (size_t)t * tstr;
        bool wh = (dir == 0) ? (s == T_SEQ - 1) : (s == 0);
#pragma unroll
        for (int it = 0; it < 2; it++) {
            int idx = it * 256 + tid;
            int b = idx >> 3, jj = idx & 7, col = j0 + jj;
            const float* p0 = sRed + b * 34;
            const float* p1 = sRed + 64 * 34 + b * 34;
            const float* gx = sGx + b * 36;
            float ig = p0[jj]      + p1[jj]      + gx[jj];
            float fg = p0[8 + jj]  + p1[8 + jj]  + gx[8 + jj];
            float gg = p0[16 + jj] + p1[16 + jj] + gx[16 + jj];
            float og = p0[24 + jj] + p1[24 + jj] + gx[24 + jj];
            float cn = sigm(fg) * creg[it] + sigm(ig) * tanh_fast(gg);
            float hn = sigm(og) * tanh_fast(cn);
            creg[it] = cn;
            hrow[(size_t)b * ldh + col] = hn;
            if (wh) {
                hidh[b * 1024 + col] = hn;
                hidc[b * 1024 + col] = cn;
            }
        }

        // publish step completion: all stores -> syncthreads -> release store
        __syncthreads();
        if (tid == 0) flag_release(myflag, (unsigned)(s + 1));
    }
}

// ---------------- host -------------------------------------------------------
extern "C" void kernel_launch(void* const* d_in, const int* in_sizes, int n_in,
                              void* d_out, int out_size) {
    const float* x     = (const float*)d_in[0];
    const float* wihf0 = (const float*)d_in[1];
    const float* whhf0 = (const float*)d_in[2];
    const float* wihf1 = (const float*)d_in[3];
    const float* whhf1 = (const float*)d_in[4];
    const float* wihb0 = (const float*)d_in[5];
    const float* whhb0 = (const float*)d_in[6];
    const float* wihb1 = (const float*)d_in[7];
    const float* whhb1 = (const float*)d_in[8];
    float* out = (float*)d_out;

    float *gates0, *gates1, *H0, *H1;
    cudaGetSymbolAddress((void**)&gates0, g_gatesF);
    cudaGetSymbolAddress((void**)&gates1, g_gatesB);
    cudaGetSymbolAddress((void**)&H0, g_H0buf);
    cudaGetSymbolAddress((void**)&H1, g_H1buf);

    const int PRE_SMEM = 73728;
    const int PERSIST_SMEM = (64 * AROW + 32 * WROW + 2 * 64 * 34 + 64 * 36) * 4;  // 225280
    cudaFuncSetAttribute(pre_gemm, cudaFuncAttributeMaxDynamicSharedMemorySize, PRE_SMEM);
    cudaFuncSetAttribute(lstm_persist, cudaFuncAttributeMaxDynamicSharedMemorySize, PERSIST_SMEM);

    // Launch map (harness prepends 2 internal launches; ncu -s 5 captures OUR #3):
    //  #0 preL0(z2)  #1 reset  #2 noop  #3 persistL0  #4 preL1a  #5 preL1b
    //  #6 reset  #7 persistL1
    pre_gemm<<<dim3(16, 512, 2), 256, PRE_SMEM>>>(x, x, wihf0, wihb0, gates0, gates1);
    reset_bar<<<16, 256>>>();
    noop<<<1, 1>>>();
    {
        PersistArgs pa;
        pa.W[0] = whhf0;  pa.W[1] = whhb0;
        pa.Gx[0] = gates0; pa.Gx[1] = gates1;
        pa.Hout[0] = H0;  pa.Hout[1] = H1;
        pa.hid_h[0] = out + HIDH_OFF;       pa.hid_h[1] = out + HIDH_OFF + 512;
        pa.hid_c[0] = out + HIDC_OFF;       pa.hid_c[1] = out + HIDC_OFF + 512;
        pa.ldh = 512;
        lstm_persist<<<dim3(64, 2), 256, PERSIST_SMEM>>>(pa);
    }

    // layer 1: different inputs per direction -> two z=1 launches (R7 pattern)
    pre_gemm<<<dim3(16, 512, 1), 256, PRE_SMEM>>>(H0, H0, wihf1, wihf1, gates0, gates0);
    pre_gemm<<<dim3(16, 512, 1), 256, PRE_SMEM>>>(H1, H1, wihb1, wihb1, gates1, gates1);
    reset_bar<<<16, 256>>>();
    {
        PersistArgs pa;
        pa.W[0] = whhf1;  pa.W[1] = whhb1;
        pa.Gx[0] = gates0; pa.Gx[1] = gates1;
        pa.Hout[0] = out; pa.Hout[1] = out + 512;
        pa.hid_h[0] = out + HIDH_OFF + 65536;  pa.hid_h[1] = out + HIDH_OFF + 65536 + 512;
        pa.hid_c[0] = out + HIDC_OFF + 65536;  pa.hid_c[1] = out + HIDC_OFF + 65536 + 512;
        pa.ldh = 1024;
        lstm_persist<<<dim3(64, 2), 256, PERSIST_SMEM>>>(pa);
    }
    (void)in_sizes; (void)n_in; (void)out_size;
}